// round 10
// baseline (speedup 1.0000x reference)
#include <cuda_runtime.h>

// DegreePrediction: y[u] = sum_{s,t,v} (x*W_t)[s,t] * (W_r*r_zeros + r_const)[s,t,u,v]
// N = 80. Three 80^4 fp32 tensors (491.5 MB) streamed once.
//
// R10: persistent blocks (GRID=592 = 148 SMs x 4, single wave) over CONTIGUOUS
// slice runs. Each block streams 3 linear regions with pointer-increment
// addressing (+5120 B/iter), register prefetch pipeline carried across slice
// boundaries, epilogue exactly once per block. Fixes R9's ALU-heavy strided
// addressing (alu 5.0%) while keeping its 592-epilogue / zero-wave structure.
//
// Layout: slice = 1600 contiguous float4 = 5*320; run starts slice-aligned, so
// iteration it reads float4 (tid + 320*it) and u = tid/20 + 16*(it mod 5).

#define NN 80
#define SLICE_F4 1600               // float4 per slice
#define THREADS 320
#define J_ITERS 5
#define TOTAL_SLICES (NN * NN)      // 6400
#define GRID 592                    // 148 SMs * 4 blocks, single wave
#define NS_BASE (TOTAL_SLICES / GRID)        // 10
#define NS_REM  (TOTAL_SLICES - GRID * NS_BASE)  // 480 blocks get 11

__device__ float    g_scratch[NN];   // zero at load; kernel keeps it net-zero
__device__ unsigned g_count;         // ditto

__device__ __forceinline__ unsigned atom_inc_acq_rel(unsigned* p) {
    unsigned old;
    asm volatile("atom.add.acq_rel.gpu.global.u32 %0, [%1], 1;"
                 : "=r"(old) : "l"(p) : "memory");
    return old;
}

__global__ __launch_bounds__(THREADS, 4)
void degree_pred_kernel(const float* __restrict__ x,
                        const float* __restrict__ r_zeros,
                        const float* __restrict__ r_const,
                        const float* __restrict__ weights_t,
                        const float* __restrict__ weights_r,
                        float* __restrict__ out)
{
    __shared__ float y_part[J_ITERS][THREADS];
    __shared__ bool is_last;
    const int tid = threadIdx.x;
    const int bid = blockIdx.x;

    // contiguous run: block bid owns slices [s0, s0+ns)
    const int ns = NS_BASE + (bid < NS_REM ? 1 : 0);
    const int s0 = bid * NS_BASE + (bid < NS_REM ? bid : NS_REM);

    const size_t fbase = (size_t)s0 * SLICE_F4 + tid;
    const float4* __restrict__ pz = reinterpret_cast<const float4*>(r_zeros)   + fbase;
    const float4* __restrict__ pc = reinterpret_cast<const float4*>(r_const)   + fbase;
    const float4* __restrict__ pw = reinterpret_cast<const float4*>(weights_r) + fbase;

    float acc[J_ITERS];
#pragma unroll
    for (int j = 0; j < J_ITERS; j++) acc[j] = 0.0f;

    // prologue: prefetch iteration 0 and the first slice scalar
    float a_cur = __ldg(&x[s0]) * __ldg(&weights_t[s0]);
    float4 z0 = __ldcs(pz);
    float4 c0 = __ldcs(pc);
    float4 w0 = __ldcs(pw);

    for (int ss = 0; ss < ns; ss++) {
        const bool last_slice = (ss == ns - 1);
        const int sn = last_slice ? (s0 + ss) : (s0 + ss + 1);
        const float a_next = __ldg(&x[sn]) * __ldg(&weights_t[sn]);

#pragma unroll
        for (int j = 0; j < J_ITERS; j++) {
            pz += THREADS; pc += THREADS; pw += THREADS;   // next iter's data

            float4 z1, c1, w1;
            if (j < J_ITERS - 1 || !last_slice) {          // j<4: always true
                z1 = __ldcs(pz);
                c1 = __ldcs(pc);
                w1 = __ldcs(pw);
            }

            float t = (c0.x + c0.y) + (c0.z + c0.w);
            t = fmaf(w0.x, z0.x, t);
            t = fmaf(w0.y, z0.y, t);
            t = fmaf(w0.z, z0.z, t);
            t = fmaf(w0.w, z0.w, t);
            acc[j] = fmaf(a_cur, t, acc[j]);

            z0 = z1; c0 = c1; w0 = w1;
        }
        a_cur = a_next;
    }

    // ---- epilogue (once per block): STS transpose + 80-thread gather ----
#pragma unroll
    for (int j = 0; j < J_ITERS; j++)
        y_part[j][tid] = acc[j];
    __syncthreads();

    if (tid < NN) {
        const int u = tid;
        const int j = u >> 4;            // u / 16
        const int b = (u & 15) * 20;     // first of 20 contributing threads
        float s = 0.0f;
#pragma unroll
        for (int d = 0; d < 20; d++)
            s += y_part[j][b + d];
        atomicAdd(&g_scratch[u], s);     // relaxed; published by acq_rel below
    }
    __syncthreads();

    // ---- last-block finalize (no full membar, no L1 flush) ----
    if (tid == 0)
        is_last = (atom_inc_acq_rel(&g_count) == (unsigned)(GRID - 1));
    __syncthreads();

    if (is_last) {
        if (tid < NN) {
            float v = __ldcg(&g_scratch[tid]);   // L2 read, coherent w/ atomics
            out[tid] = v;
            g_scratch[tid] = 0.0f;               // restore initial state
        }
        __syncthreads();
        if (tid == 0) g_count = 0u;              // restore initial state
    }
}

extern "C" void kernel_launch(void* const* d_in, const int* in_sizes, int n_in,
                              void* d_out, int out_size)
{
    const float* x         = (const float*)d_in[0];
    const float* r_zeros   = (const float*)d_in[1];
    const float* r_const   = (const float*)d_in[2];
    const float* weights_t = (const float*)d_in[3];
    const float* weights_r = (const float*)d_in[4];
    float* out = (float*)d_out;

    degree_pred_kernel<<<GRID, THREADS>>>(x, r_zeros, r_const,
                                          weights_t, weights_r, out);
}